// round 15
// baseline (speedup 1.0000x reference)
#include <cuda_runtime.h>

#define NROWS 256
#define QPR   4                       // quarter-row units per row
#define RBLK  (NROWS * QPR)           // 1024 reduce blocks
#define TPB   256

// Scratch (no cudaMalloc). Zero-init at module load.
__device__ float d_partial[NROWS * QPR];
__device__ float d_row_mean[NROWS];
__device__ unsigned int d_count[NROWS];           // reduce arrivals
__device__ volatile unsigned int d_ready[NROWS];  // mean published
__device__ unsigned int d_done[NROWS];            // scale completions

// Single kernel, 2048 blocks. Blocks [0,1024): reduce quarter-rows of conv1
// (never wait). Blocks [1024,2048): scale quarter-rows of conv2 (wait on the
// row's mean flag). Dispatch is blockIdx-ordered, so every waiter depends only
// on strictly-earlier blocks -> deadlock-free; by the time scale blocks become
// resident their means are (almost always) already published.
__global__ __launch_bounds__(TPB) void pipe_kernel(const float* __restrict__ c1,
                                                   const float* __restrict__ c2,
                                                   float* __restrict__ out,
                                                   int row_elems) {
    const int bid = blockIdx.x;
    const int tid = threadIdx.x;
    const int n4 = row_elems >> 2;        // 12544
    const int q4 = n4 >> 2;               // 3136 float4 per quarter

    if (bid < RBLK) {
        // ---------------- Reduce quarter ----------------
        const int row = bid >> 2;
        const int q   = bid & 3;
        const float4* p = reinterpret_cast<const float4*>(c1 + (size_t)row * row_elems)
                          + q * q4;

        float s0 = 0.f, s1 = 0.f, s2 = 0.f, s3 = 0.f;
        if (q4 == 3136) {
            #pragma unroll
            for (int k = 0; k < 3; k++) {       // 12 strides of 256 = 3072
                const int b = k * 1024 + tid;
                float4 a0 = __ldcs(&p[b]);
                float4 a1 = __ldcs(&p[b + 256]);
                float4 a2 = __ldcs(&p[b + 512]);
                float4 a3 = __ldcs(&p[b + 768]);
                s0 += (a0.x + a0.y) + (a0.z + a0.w);
                s1 += (a1.x + a1.y) + (a1.z + a1.w);
                s2 += (a2.x + a2.y) + (a2.z + a2.w);
                s3 += (a3.x + a3.y) + (a3.z + a3.w);
            }
            if (tid < 64) {                      // tail 3072..3135
                float4 a = __ldcs(&p[3072 + tid]);
                s0 += (a.x + a.y) + (a.z + a.w);
            }
        } else {
            for (int i = tid; i < q4; i += TPB) {
                float4 a = __ldcs(&p[i]);
                s0 += (a.x + a.y) + (a.z + a.w);
            }
        }
        float s = (s0 + s1) + (s2 + s3);

        #pragma unroll
        for (int o = 16; o > 0; o >>= 1)
            s += __shfl_xor_sync(0xffffffffu, s, o);

        __shared__ float warp_sums[8];
        const int lane = tid & 31;
        const int wid  = tid >> 5;
        if (lane == 0) warp_sums[wid] = s;
        __syncthreads();

        if (tid == 0) {
            float t = 0.f;
            #pragma unroll
            for (int w = 0; w < 8; w++) t += warp_sums[w];

            d_partial[row * QPR + q] = t;
            __threadfence();
            unsigned int old = atomicAdd(&d_count[row], 1u);
            if (old == QPR - 1) {
                // Fixed-order sum -> deterministic mean.
                const volatile float* vp = d_partial + row * QPR;
                float sum = 0.f;
                #pragma unroll
                for (int k = 0; k < QPR; k++) sum += vp[k];
                d_row_mean[row] = sum / (float)row_elems;
                d_count[row] = 0;              // self-reset for next replay
                __threadfence();
                d_ready[row] = 1;              // publish
            }
        }
    } else {
        // ---------------- Scale quarter ----------------
        const int sbid = bid - RBLK;
        const int row = sbid >> 2;
        const int q   = sbid & 3;
        const size_t base = (size_t)row * row_elems;
        const float4* src = reinterpret_cast<const float4*>(c2 + base) + q * q4;
        float4* dst       = reinterpret_cast<float4*>(out + base) + q * q4;

        if (tid == 0) {
            while (d_ready[row] == 0) __nanosleep(32);
        }
        __syncthreads();
        __threadfence();
        const float m = *((volatile float*)&d_row_mean[row]);

        if (q4 == 3136) {
            #pragma unroll
            for (int k = 0; k < 3; k++) {
                const int b = k * 1024 + tid;
                float4 a0 = __ldcs(&src[b]);
                float4 a1 = __ldcs(&src[b + 256]);
                float4 a2 = __ldcs(&src[b + 512]);
                float4 a3 = __ldcs(&src[b + 768]);
                a0.x *= m; a0.y *= m; a0.z *= m; a0.w *= m;
                a1.x *= m; a1.y *= m; a1.z *= m; a1.w *= m;
                a2.x *= m; a2.y *= m; a2.z *= m; a2.w *= m;
                a3.x *= m; a3.y *= m; a3.z *= m; a3.w *= m;
                __stcs(&dst[b],       a0);
                __stcs(&dst[b + 256], a1);
                __stcs(&dst[b + 512], a2);
                __stcs(&dst[b + 768], a3);
            }
            if (tid < 64) {
                float4 a = __ldcs(&src[3072 + tid]);
                a.x *= m; a.y *= m; a.z *= m; a.w *= m;
                __stcs(&dst[3072 + tid], a);
            }
        } else {
            for (int i = tid; i < q4; i += TPB) {
                float4 a = __ldcs(&src[i]);
                a.x *= m; a.y *= m; a.z *= m; a.w *= m;
                __stcs(&dst[i], a);
            }
        }

        __syncthreads();
        if (tid == 0) {
            unsigned int o = atomicAdd(&d_done[row], 1u);
            if (o == QPR - 1) {                // last scale quarter of this row
                d_ready[row] = 0;              // self-reset for next replay
                d_done[row] = 0;
            }
        }
    }
}

extern "C" void kernel_launch(void* const* d_in, const int* in_sizes, int n_in,
                              void* d_out, int out_size) {
    const float* c1 = (const float*)d_in[0];
    const float* c2 = (const float*)d_in[1];
    float* out = (float*)d_out;

    const int row_elems = in_sizes[0] / NROWS;  // 50176

    pipe_kernel<<<2 * RBLK, TPB>>>(c1, c2, out, row_elems);
}